// round 7
// baseline (speedup 1.0000x reference)
#include <cuda_runtime.h>

// LearnableWatershedWithSDF — exact closed form.
//
// The reference's flood loop is p <- softmax(avgpool3(p) + bias), with bias
// channel-constant per pixel (softmax shift-invariance => bias is a no-op).
// Each iteration contracts the channel logit spread by ~16x; within ~10-12 of
// the 50 iterations every pixel reaches the EXACT fp32 fixed point: all 16
// probabilities identically 1/16 (logit differences underflow to 0, exp(0)=1,
// 0.0625 exact in binary). jnp.argmax (first-index ties) of exact-uniform = 0
// at every pixel, for ANY input. Empirically confirmed: a faithful
// 50-iteration fp32 implementation and a 16-iteration __expf implementation
// both returned rel_err == 0.0 (bit-identical labels) vs the JAX reference.
// The function is identically zero; the kernel is a 2 MB zero-fill.
//
// Config sweep (wall / kernel us): 512x256x1+pred 5.12/3.87; memset node
// 6.11/-; 128x256x4 5.22/4.16; 128x1024x1 5.86/3.74. Wall is launch/replay
// floor + noise; best geometry was 512x256x1. This round keeps that geometry
// and drops the bounds predicate on the exact-fit path (one bare STG.128 per
// thread, shortest possible SASS).

// Exact-fit: 256 threads/block, one int4 (16 B) per thread, no predication.
__global__ __launch_bounds__(256) void k_zero256(int4* __restrict__ out) {
    out[(size_t)blockIdx.x * 256 + threadIdx.x] = make_int4(0, 0, 0, 0);
}

// Generic fallback: grid-stride int fill (any out_size).
__global__ __launch_bounds__(256) void k_zero_any(int* __restrict__ out, int n) {
    for (int i = blockIdx.x * 256 + threadIdx.x; i < n; i += gridDim.x * 256)
        out[i] = 0;
}

extern "C" void kernel_launch(void* const* d_in, const int* in_sizes, int n_in,
                              void* d_out, int out_size) {
    (void)d_in; (void)in_sizes; (void)n_in;
    const int QUANT = 1024;                 // ints per block (256 x int4)
    if (out_size > 0 && (out_size & (QUANT - 1)) == 0) {
        k_zero256<<<out_size / QUANT, 256>>>((int4*)d_out);
    } else {
        int blocks = (out_size + 255) / 256;
        if (blocks > 1024) blocks = 1024;
        if (blocks < 1) blocks = 1;
        k_zero_any<<<blocks, 256>>>((int*)d_out, out_size);
    }
}

// round 8
// speedup vs baseline: 1.1720x; 1.1720x over previous
#include <cuda_runtime.h>

// LearnableWatershedWithSDF — exact closed form. TERMINAL.
//
// Math: the flood loop is p <- softmax(avgpool3(p) + bias), bias channel-
// constant per pixel (softmax shift-invariance => bias is a no-op). Each
// iteration contracts channel logit spread by ~16x; within ~10-12 of the 50
// iterations every pixel reaches the EXACT fp32 fixed point: all 16 probs
// identically 1/16 (logit deltas underflow to 0, exp(0)=1, 0.0625 exact in
// binary; uniform is invariant under pooling+softmax). jnp.argmax (first-index
// ties) of exact-uniform = 0 at every pixel, for ANY input.
//
// Verification: a faithful 50-iteration fp32 implementation (R0) and an
// independent 16-iteration __expf implementation (R1) both produced
// rel_err == 0.0 (bit-identical int labels) vs the JAX reference.
// The function is identically zero; the kernel is a 2 MB zero-fill.
//
// Floor evidence (wall us): 512x256+pred 5.12 | 128x256x4 5.22 | 128x1024
// 5.86 | 512x256 no-pred 5.89 | memset node 6.11. Spread >> config effects:
// all points sit at the graph-replay + launch/drain floor with +-0.5us noise.
// Submitting the best-measured configuration (R3).

__global__ __launch_bounds__(256) void k_zero(int4* __restrict__ out, int n4) {
    int i = blockIdx.x * 256 + threadIdx.x;
    if (i < n4) out[i] = make_int4(0, 0, 0, 0);
}

__global__ __launch_bounds__(256) void k_zero_tail(int* __restrict__ out,
                                                   int start, int n) {
    int i = start + blockIdx.x * 256 + threadIdx.x;
    if (i < n) out[i] = 0;
}

extern "C" void kernel_launch(void* const* d_in, const int* in_sizes, int n_in,
                              void* d_out, int out_size) {
    (void)d_in; (void)in_sizes; (void)n_in;
    int n4 = out_size >> 2;                 // vectorized int4 stores
    if (n4 > 0) {
        int blocks = (n4 + 255) / 256;
        k_zero<<<blocks, 256>>>((int4*)d_out, n4);
    }
    int done = n4 << 2;
    if (done < out_size) {                  // tail (out_size not multiple of 4)
        int rem = out_size - done;
        int blocks = (rem + 255) / 256;
        k_zero_tail<<<blocks, 256>>>((int*)d_out, done, out_size);
    }
}